// round 9
// baseline (speedup 1.0000x reference)
#include <cuda_runtime.h>
#include <cuda_bf16.h>

#define B_ 32
#define N_ 256
#define TAIL_FR 8
#define TAIL_BYTES (TAIL_FR * 2048)   // 8 frames x 2KB = 16KB smem zero buffer

__device__ __forceinline__ unsigned smem_u32(const void* p) {
    unsigned a;
    asm("{ .reg .u64 t; cvta.to.shared.u64 t, %1; cvt.u32.u64 %0, t; }"
        : "=r"(a) : "l"(p));
    return a;
}

// ---------------------------------------------------------------------------
// Single fused kernel. Grid (N_ + ceil(T/TAIL_FR), B_), 128 threads.
//   blockIdx.x <  N_  -> segment block (b, idx): derive c0/c1/d by block
//                        reduction over the durations row, load <=3 source
//                        rows once, stream-store all d frames (__stcs path).
//   blockIdx.x >= N_  -> tail block: mask write + zero-fill of the inactive
//                        sub-range via TMA bulk store (SMEM->L2, bypasses the
//                        L1tex STG path).
// int32/int64 detection: durations < 16, so if int64 every odd 32-bit word of
// the first 512 words is 0 (region in-bounds under both layouts).
// All reductions/barriers complete before any divergent exit.
// ---------------------------------------------------------------------------
__global__ __launch_bounds__(128) void main_kernel(
    const float4* __restrict__ start,
    const float4* __restrict__ mid,
    const float4* __restrict__ end,
    const void* __restrict__ dur_raw,
    const void* __restrict__ rc_raw,
    float4* __restrict__ out,
    float* __restrict__ mask_out,
    int T, int F4, int write_mask)
{
    const int b   = blockIdx.y;
    const int tid = threadIdx.x;
    const bool is_seg = (blockIdx.x < N_);
    const int idx = is_seg ? blockIdx.x : -1;

    __shared__ int shO[4];
    __shared__ int shC[4], shD[4], shT[4];
    __shared__ __align__(16) float4 zbuf[TAIL_BYTES / 16];

    // ---- detect int32 vs int64 (first 512 words, broadcast/L1-hot) ----
    const int4* d4 = (const int4*)dur_raw;
    int4 det = __ldg(d4 + tid);
    int odd = det.y | det.w;
    odd = __reduce_or_sync(0xffffffffu, odd);
    if ((tid & 31) == 0) shO[tid >> 5] = odd;
    __syncthreads();
    const int is64 = ((shO[0] | shO[1] | shO[2] | shO[3]) == 0) ? 1 : 0;
    __syncthreads();

    // ---- load this batch's durations, predicated accumulate ----
    int accC = 0, accD = 0, accT = 0;
    if (is64) {
        int4 w = __ldg(d4 + b * 128 + tid);
        const int e0 = 2 * tid, e1 = 2 * tid + 1;
        accT = w.x + w.z;
        if (e0 <= idx) accC += w.x;
        if (e1 <= idx) accC += w.z;
        if (e0 == idx) accD += w.x;
        if (e1 == idx) accD += w.z;
    } else if (tid < 64) {
        int4 w = __ldg(d4 + b * 64 + tid);
        const int e0 = 4 * tid;
        accT = w.x + w.y + w.z + w.w;
        if (e0 + 0 <= idx) accC += w.x;
        if (e0 + 1 <= idx) accC += w.y;
        if (e0 + 2 <= idx) accC += w.z;
        if (e0 + 3 <= idx) accC += w.w;
        if (e0 + 0 == idx) accD += w.x;
        if (e0 + 1 == idx) accD += w.y;
        if (e0 + 2 == idx) accD += w.z;
        if (e0 + 3 == idx) accD += w.w;
    }
    accC = __reduce_add_sync(0xffffffffu, accC);
    accD = __reduce_add_sync(0xffffffffu, accD);
    accT = __reduce_add_sync(0xffffffffu, accT);
    if ((tid & 31) == 0) {
        shC[tid >> 5] = accC; shD[tid >> 5] = accD; shT[tid >> 5] = accT;
    }
    __syncthreads();
    const int c1     = shC[0] + shC[1] + shC[2] + shC[3];
    const int d      = shD[0] + shD[1] + shD[2] + shD[3];
    const int totalF = shT[0] + shT[1] + shT[2] + shT[3];

    const int f0 = tid;

    if (!is_seg) {
        // ---- tail / mask block: frames [tb, tb+TAIL_FR) ----
        const int tb = (blockIdx.x - N_) * TAIL_FR;
        int total = totalF; if (total > T) total = T;
        if (write_mask && f0 < TAIL_FR && tb + f0 < T) {
            mask_out[b * T + tb + f0] = (tb + f0 < total) ? 1.0f : 0.0f;
        }
        int zs = tb; if (zs < total) zs = total;   // zero range [zs, ze)
        int ze = tb + TAIL_FR; if (ze > T) ze = T;
        if (zs >= ze) return;

        // zero the smem staging buffer (full 16KB; only (ze-zs) frames used)
        const float4 z = make_float4(0.f, 0.f, 0.f, 0.f);
#pragma unroll
        for (int k = 0; k < TAIL_BYTES / 16 / 128; ++k)
            zbuf[k * 128 + f0] = z;
        __syncthreads();

        if (tid == 0) {
            const unsigned sa = smem_u32(zbuf);
            const unsigned bytes = (unsigned)(ze - zs) * (unsigned)(F4 * 16);
            float4* gdst = out + (b * T + zs) * F4;
            asm volatile("fence.proxy.async.shared::cta;" ::: "memory");
            asm volatile(
                "cp.async.bulk.global.shared::cta.bulk_group [%0], [%1], %2;"
                :: "l"(gdst), "r"(sa), "r"(bytes) : "memory");
            asm volatile("cp.async.bulk.commit_group;" ::: "memory");
            asm volatile("cp.async.bulk.wait_group 0;" ::: "memory");
        }
        return;
    }

    // ---- segment block ----
    if (d <= 0) return;
    const int off = c1 - d;
    if (off >= T) return;

    const int cls = is64 ? (int)((const long long*)rc_raw)[b * N_ + idx]
                         : ((const int*)rc_raw)[b * N_ + idx];
    const bool lin = (cls == 1) && (d >= 4);

    const int rb = (b * N_ + idx) * F4 + f0;
    const bool need_s = lin || (d > 1);
    const bool need_e = lin || (d > 1);
    const bool need_m = lin || (d != 2);
    float4 s, m, e;
    if (need_s) s = __ldg(start + rb);
    if (need_m) m = __ldg(mid + rb);
    if (need_e) e = __ldg(end + rb);

    int pe = d; if (off + pe > T) pe = T - off;
    const int half = d >> 1;
    int den1 = half - 1;     if (den1 < 1) den1 = 1;
    int den2 = d - half - 1; if (den2 < 1) den2 = 1;
    const float inv1 = 1.0f / (float)den1;
    const float inv2 = 1.0f / (float)den2;

    float4* __restrict__ ob = out + (b * T + off) * F4 + f0;

    if (lin) {
#pragma unroll 4
        for (int p = 0; p < pe; ++p) {
            const bool fh = (p < half);
            const float w1 = fh ? (float)p * inv1 : (float)(p - half) * inv2;
            const float w0 = 1.0f - w1;
            const float4 A  = fh ? s : m;
            const float4 Bv = fh ? m : e;
            float4 r;
            r.x = fmaf(A.x, w0, Bv.x * w1);
            r.y = fmaf(A.y, w0, Bv.y * w1);
            r.z = fmaf(A.z, w0, Bv.z * w1);
            r.w = fmaf(A.w, w0, Bv.w * w1);
            __stcs(ob + p * F4, r);
        }
    } else {
#pragma unroll 4
        for (int p = 0; p < pe; ++p) {
            float4 r = m;
            if (d > 1) {
                if (p == 0)          r = s;
                else if (p == d - 1) r = e;
            }
            __stcs(ob + p * F4, r);
        }
    }
}

// ---------------------------------------------------------------------------
// Launch
// ---------------------------------------------------------------------------
extern "C" void kernel_launch(void* const* d_in, const int* in_sizes, int n_in,
                              void* d_out, int out_size) {
    const float* start = (const float*)d_in[0];
    const float* mid   = (const float*)d_in[1];
    const float* end   = (const float*)d_in[2];
    const void*  dur   = d_in[3];
    const void*  rc    = d_in[4];
    (void)n_in;

    const int BN = in_sizes[3];                 // B*N
    const int F  = in_sizes[0] / BN;            // 512
    const int F4 = F / 4;

    long long os = (long long)out_size;
    int T, write_mask;
    if (os % ((long long)B_ * (F + 1)) == 0) {
        T = (int)(os / ((long long)B_ * (F + 1)));
        write_mask = 1;
    } else {
        T = (int)(os / ((long long)B_ * F));
        write_mask = 0;
    }

    float* out_f  = (float*)d_out;
    float* mask_f = out_f + B_ * T * F;

    const int tail_blocks = (T + TAIL_FR - 1) / TAIL_FR;
    dim3 grid(N_ + tail_blocks, B_);
    main_kernel<<<grid, 128>>>(
        (const float4*)start, (const float4*)mid, (const float4*)end,
        dur, rc, (float4*)out_f, mask_f, T, F4, write_mask);
}

// round 10
// speedup vs baseline: 1.0017x; 1.0017x over previous
#include <cuda_runtime.h>
#include <cuda_bf16.h>

#define B_ 32
#define N_ 256
#define TAIL_FR 32

// ---------------------------------------------------------------------------
// Single fused kernel. Grid (N_ + ceil(T/TAIL_FR), B_), 128 threads.
//   blockIdx.x <  N_  -> segment block (b, idx): derive c0/c1/d by block
//                        reduction over the durations row, load <=3 source
//                        rows once, stream-store all d frames.
//   blockIdx.x >= N_  -> tail block: 32 frames; mask write + zero-fill of the
//                        contiguous inactive sub-range (pure STG stream).
// int32/int64 detection: durations < 16, so if int64 every odd 32-bit word of
// the first 512 words is 0 (region in-bounds under both layouts).
// All reductions/barriers complete before any divergent exit.
// ---------------------------------------------------------------------------
__global__ __launch_bounds__(128) void main_kernel(
    const float4* __restrict__ start,
    const float4* __restrict__ mid,
    const float4* __restrict__ end,
    const void* __restrict__ dur_raw,
    const void* __restrict__ rc_raw,
    float4* __restrict__ out,
    float* __restrict__ mask_out,
    int T, int F4, int write_mask)
{
    const int b   = blockIdx.y;
    const int tid = threadIdx.x;
    const bool is_seg = (blockIdx.x < N_);
    const int idx = is_seg ? blockIdx.x : -1;

    __shared__ int shO[4];
    __shared__ int shC[4], shD[4], shT[4];

    // ---- detect int32 vs int64 (first 512 words, broadcast/L1-hot) ----
    const int4* d4 = (const int4*)dur_raw;
    int4 det = __ldg(d4 + tid);
    int odd = det.y | det.w;
    odd = __reduce_or_sync(0xffffffffu, odd);
    if ((tid & 31) == 0) shO[tid >> 5] = odd;
    __syncthreads();
    const int is64 = ((shO[0] | shO[1] | shO[2] | shO[3]) == 0) ? 1 : 0;
    __syncthreads();

    // ---- load this batch's durations, predicated accumulate ----
    int accC = 0, accD = 0, accT = 0;
    if (is64) {
        int4 w = __ldg(d4 + b * 128 + tid);
        const int e0 = 2 * tid, e1 = 2 * tid + 1;
        accT = w.x + w.z;
        if (e0 <= idx) accC += w.x;
        if (e1 <= idx) accC += w.z;
        if (e0 == idx) accD += w.x;
        if (e1 == idx) accD += w.z;
    } else if (tid < 64) {
        int4 w = __ldg(d4 + b * 64 + tid);
        const int e0 = 4 * tid;
        accT = w.x + w.y + w.z + w.w;
        if (e0 + 0 <= idx) accC += w.x;
        if (e0 + 1 <= idx) accC += w.y;
        if (e0 + 2 <= idx) accC += w.z;
        if (e0 + 3 <= idx) accC += w.w;
        if (e0 + 0 == idx) accD += w.x;
        if (e0 + 1 == idx) accD += w.y;
        if (e0 + 2 == idx) accD += w.z;
        if (e0 + 3 == idx) accD += w.w;
    }
    accC = __reduce_add_sync(0xffffffffu, accC);
    accD = __reduce_add_sync(0xffffffffu, accD);
    accT = __reduce_add_sync(0xffffffffu, accT);
    if ((tid & 31) == 0) {
        shC[tid >> 5] = accC; shD[tid >> 5] = accD; shT[tid >> 5] = accT;
    }
    __syncthreads();
    const int c1     = shC[0] + shC[1] + shC[2] + shC[3];
    const int d      = shD[0] + shD[1] + shD[2] + shD[3];
    const int totalF = shT[0] + shT[1] + shT[2] + shT[3];

    const int f0 = tid;

    if (!is_seg) {
        // ---- tail / mask block: frames [tb, tb+TAIL_FR) ----
        const int tb = (blockIdx.x - N_) * TAIL_FR;
        int total = totalF; if (total > T) total = T;
        if (write_mask && f0 < TAIL_FR && tb + f0 < T) {
            mask_out[b * T + tb + f0] = (tb + f0 < total) ? 1.0f : 0.0f;
        }
        if (tb + TAIL_FR <= total) return;    // fully active: nothing to zero
        const float4 z = make_float4(0.f, 0.f, 0.f, 0.f);
        const int ob = (b * T + tb) * F4 + f0;
#pragma unroll 8
        for (int k = 0; k < TAIL_FR; ++k) {
            const int t = tb + k;
            if (t >= total && t < T) __stcs(out + ob + k * F4, z);
        }
        return;
    }

    // ---- segment block ----
    if (d <= 0) return;
    const int off = c1 - d;
    if (off >= T) return;

    const int cls = is64 ? (int)((const long long*)rc_raw)[b * N_ + idx]
                         : ((const int*)rc_raw)[b * N_ + idx];
    const bool lin = (cls == 1) && (d >= 4);

    const int rb = (b * N_ + idx) * F4 + f0;
    const bool need_s = lin || (d > 1);
    const bool need_e = lin || (d > 1);
    const bool need_m = lin || (d != 2);
    float4 s, m, e;
    if (need_s) s = __ldg(start + rb);
    if (need_m) m = __ldg(mid + rb);
    if (need_e) e = __ldg(end + rb);

    int pe = d; if (off + pe > T) pe = T - off;
    const int half = d >> 1;
    int den1 = half - 1;     if (den1 < 1) den1 = 1;
    int den2 = d - half - 1; if (den2 < 1) den2 = 1;
    const float inv1 = 1.0f / (float)den1;
    const float inv2 = 1.0f / (float)den2;

    float4* __restrict__ ob = out + (b * T + off) * F4 + f0;

    if (lin) {
#pragma unroll 4
        for (int p = 0; p < pe; ++p) {
            const bool fh = (p < half);
            const float w1 = fh ? (float)p * inv1 : (float)(p - half) * inv2;
            const float w0 = 1.0f - w1;
            const float4 A  = fh ? s : m;
            const float4 Bv = fh ? m : e;
            float4 r;
            r.x = fmaf(A.x, w0, Bv.x * w1);
            r.y = fmaf(A.y, w0, Bv.y * w1);
            r.z = fmaf(A.z, w0, Bv.z * w1);
            r.w = fmaf(A.w, w0, Bv.w * w1);
            __stcs(ob + p * F4, r);
        }
    } else {
#pragma unroll 4
        for (int p = 0; p < pe; ++p) {
            float4 r = m;
            if (d > 1) {
                if (p == 0)          r = s;
                else if (p == d - 1) r = e;
            }
            __stcs(ob + p * F4, r);
        }
    }
}

// ---------------------------------------------------------------------------
// Launch
// ---------------------------------------------------------------------------
extern "C" void kernel_launch(void* const* d_in, const int* in_sizes, int n_in,
                              void* d_out, int out_size) {
    const float* start = (const float*)d_in[0];
    const float* mid   = (const float*)d_in[1];
    const float* end   = (const float*)d_in[2];
    const void*  dur   = d_in[3];
    const void*  rc    = d_in[4];
    (void)n_in;

    const int BN = in_sizes[3];                 // B*N
    const int F  = in_sizes[0] / BN;            // 512
    const int F4 = F / 4;

    long long os = (long long)out_size;
    int T, write_mask;
    if (os % ((long long)B_ * (F + 1)) == 0) {
        T = (int)(os / ((long long)B_ * (F + 1)));
        write_mask = 1;
    } else {
        T = (int)(os / ((long long)B_ * F));
        write_mask = 0;
    }

    float* out_f  = (float*)d_out;
    float* mask_f = out_f + B_ * T * F;

    const int tail_blocks = (T + TAIL_FR - 1) / TAIL_FR;
    dim3 grid(N_ + tail_blocks, B_);
    main_kernel<<<grid, 128>>>(
        (const float4*)start, (const float4*)mid, (const float4*)end,
        dur, rc, (float4*)out_f, mask_f, T, F4, write_mask);
}